// round 5
// baseline (speedup 1.0000x reference)
#include <cuda_runtime.h>
#include <cuda_bf16.h>
#include <float.h>
#include <stdint.h>

#define N_NODES 100000
#define N_EDGES 1600000
#define D 128
#define KDIM 256

// ---------------------------------------------------------------------------
// Device scratch (static per harness rules)
// ---------------------------------------------------------------------------
__device__ float g_agg[(size_t)N_NODES * D];
__device__ int   g_deg[N_NODES];
__device__ int   g_off[N_NODES];
__device__ int   g_rank[N_EDGES];
__device__ int   g_adj[N_EDGES];
__device__ int   g_bsum[128];
__device__ int   g_bsumoff[128];
__device__ __align__(16) __nv_bfloat16 g_Wh[128 * KDIM];  // W split hi
__device__ __align__(16) __nv_bfloat16 g_Wl[128 * KDIM];  // W split lo

// ===========================================================================
// CSR build
// ===========================================================================
__global__ void __launch_bounds__(256) zero_deg_kernel() {
    int i = blockIdx.x * blockDim.x + threadIdx.x;
    if (i < N_NODES) g_deg[i] = 0;
}

// histogram + per-edge rank (atomicAdd return value = rank within src bucket)
__global__ void __launch_bounds__(256) hist_kernel(const int* __restrict__ src) {
    int e = blockIdx.x * blockDim.x + threadIdx.x;
    if (e < N_EDGES) g_rank[e] = atomicAdd(&g_deg[src[e]], 1);
}

__global__ void __launch_bounds__(1024) scan_partial_kernel() {
    __shared__ int s[1024];
    int i = blockIdx.x * 1024 + threadIdx.x;
    int v = (i < N_NODES) ? g_deg[i] : 0;
    s[threadIdx.x] = v;
    __syncthreads();
#pragma unroll
    for (int ofs = 1; ofs < 1024; ofs <<= 1) {
        int t = (threadIdx.x >= ofs) ? s[threadIdx.x - ofs] : 0;
        __syncthreads();
        s[threadIdx.x] += t;
        __syncthreads();
    }
    if (i < N_NODES) g_off[i] = s[threadIdx.x] - v;
    if (threadIdx.x == 1023) g_bsum[blockIdx.x] = s[1023];
}

__global__ void __launch_bounds__(128) scan_bsums_kernel(int nblocks) {
    __shared__ int s[128];
    int v = (threadIdx.x < nblocks) ? g_bsum[threadIdx.x] : 0;
    s[threadIdx.x] = v;
    __syncthreads();
#pragma unroll
    for (int ofs = 1; ofs < 128; ofs <<= 1) {
        int t = (threadIdx.x >= ofs) ? s[threadIdx.x - ofs] : 0;
        __syncthreads();
        s[threadIdx.x] += t;
        __syncthreads();
    }
    g_bsumoff[threadIdx.x] = s[threadIdx.x] - v;
}

__global__ void __launch_bounds__(256) scan_add_kernel() {
    int i = blockIdx.x * blockDim.x + threadIdx.x;
    if (i < N_NODES) g_off[i] += g_bsumoff[i >> 10];
}

// atomic-free scatter using precomputed rank
__global__ void __launch_bounds__(256) fill_adj_kernel(const int* __restrict__ src,
                                                       const int* __restrict__ dst) {
    int e = blockIdx.x * blockDim.x + threadIdx.x;
    if (e < N_EDGES) {
        g_adj[g_off[src[e]] + g_rank[e]] = dst[e];
    }
}

// ===========================================================================
// Aggregate: one warp per node, gather-max over CSR neighbors. No atomics.
// ===========================================================================
__device__ __forceinline__ float4 max4(float4 a, float4 b) {
    return make_float4(fmaxf(a.x, b.x), fmaxf(a.y, b.y),
                       fmaxf(a.z, b.z), fmaxf(a.w, b.w));
}

__global__ void __launch_bounds__(256) aggregate_kernel(const float* __restrict__ H) {
    int node = (int)((blockIdx.x * blockDim.x + threadIdx.x) >> 5);
    int lane = threadIdx.x & 31;
    if (node >= N_NODES) return;

    int off = g_off[node];
    int deg = g_deg[node];

    float4 m = make_float4(-FLT_MAX, -FLT_MAX, -FLT_MAX, -FLT_MAX);
    int j = 0;
    for (; j + 4 <= deg; j += 4) {
        int n0 = g_adj[off + j + 0];
        int n1 = g_adj[off + j + 1];
        int n2 = g_adj[off + j + 2];
        int n3 = g_adj[off + j + 3];
        float4 v0 = *reinterpret_cast<const float4*>(H + (size_t)n0 * D + lane * 4);
        float4 v1 = *reinterpret_cast<const float4*>(H + (size_t)n1 * D + lane * 4);
        float4 v2 = *reinterpret_cast<const float4*>(H + (size_t)n2 * D + lane * 4);
        float4 v3 = *reinterpret_cast<const float4*>(H + (size_t)n3 * D + lane * 4);
        m = max4(m, max4(max4(v0, v1), max4(v2, v3)));
    }
    for (; j < deg; j++) {
        int n0 = g_adj[off + j];
        float4 v0 = *reinterpret_cast<const float4*>(H + (size_t)n0 * D + lane * 4);
        m = max4(m, v0);
    }
    if (deg == 0) m = make_float4(0.f, 0.f, 0.f, 0.f);
    *reinterpret_cast<float4*>(g_agg + (size_t)node * D + lane * 4) = m;
}

// ===========================================================================
// W hi/lo bf16 split
// ===========================================================================
__global__ void __launch_bounds__(256) wsplit_kernel(const float* __restrict__ W) {
    int i = blockIdx.x * blockDim.x + threadIdx.x;
    if (i < 128 * KDIM) {
        float v = W[i];
        __nv_bfloat16 h = __float2bfloat16_rn(v);
        g_Wh[i] = h;
        g_Wl[i] = __float2bfloat16_rn(v - __bfloat162float(h));
    }
}

// ===========================================================================
// Half-K GEMM: acc = A[m][0..128) @ W[n][kofs..kofs+128)^T  (3-pass bf16 split)
//   use_agg==0: A = H (param),  kofs=0,   out = acc + bias
//   use_agg==1: A = g_agg,      kofs=128, out += acc
// A pointer selected IN-KERNEL (never pass a __device__ symbol from host!)
// CTA 256 thr: tile M=128, N=128. Warp tile 32x64. K chunks of 32.
// ===========================================================================
__device__ __forceinline__ uint32_t smem_u32(const void* p) {
    uint32_t a;
    asm("{ .reg .u64 t; cvta.to.shared.u64 t, %1; cvt.u32.u64 %0, t; }"
        : "=r"(a) : "l"(p));
    return a;
}

__device__ __forceinline__ uint32_t sw64(uint32_t b) { return b ^ ((b >> 3) & 0x30); }

__device__ __forceinline__ void ldsm_x4(uint32_t& r0, uint32_t& r1, uint32_t& r2,
                                        uint32_t& r3, uint32_t addr) {
    asm volatile("ldmatrix.sync.aligned.m8n8.x4.shared.b16 {%0,%1,%2,%3}, [%4];"
                 : "=r"(r0), "=r"(r1), "=r"(r2), "=r"(r3) : "r"(addr));
}

__device__ __forceinline__ void mma_bf16(float* c, uint32_t a0, uint32_t a1,
                                         uint32_t a2, uint32_t a3,
                                         uint32_t b0, uint32_t b1) {
    asm volatile(
        "mma.sync.aligned.m16n8k16.row.col.f32.bf16.bf16.f32 "
        "{%0,%1,%2,%3},{%4,%5,%6,%7},{%8,%9},{%0,%1,%2,%3};"
        : "+f"(c[0]), "+f"(c[1]), "+f"(c[2]), "+f"(c[3])
        : "r"(a0), "r"(a1), "r"(a2), "r"(a3), "r"(b0), "r"(b1));
}

#define KC 32

__global__ void __launch_bounds__(256) gemm_half_kernel(
    const float* __restrict__ Hin,     // used when use_agg==0
    const float* __restrict__ bias,
    float* __restrict__ out,
    int use_agg)
{
    __shared__ __align__(1024) uint8_t sAh[128 * 64];
    __shared__ __align__(1024) uint8_t sAl[128 * 64];
    __shared__ __align__(1024) uint8_t sBh[128 * 64];
    __shared__ __align__(1024) uint8_t sBl[128 * 64];

    const float* A  = use_agg ? (const float*)g_agg : Hin;
    const int   kofs = use_agg ? 128 : 0;

    const int tid    = threadIdx.x;
    const int wid    = tid >> 5;
    const int lane   = tid & 31;
    const int warp_m = wid >> 1;
    const int warp_n = wid & 1;
    const int mblk   = blockIdx.x * 128;

    const uint32_t bAh = smem_u32(sAh);
    const uint32_t bAl = smem_u32(sAl);
    const uint32_t bBh = smem_u32(sBh);
    const uint32_t bBl = smem_u32(sBl);

    const int lsub = lane >> 3;
    const int lr   = lane & 7;

    float acc[2][8][4];
#pragma unroll
    for (int f = 0; f < 2; f++)
#pragma unroll
        for (int t = 0; t < 8; t++)
#pragma unroll
            for (int i = 0; i < 4; i++) acc[f][t][i] = 0.f;

    for (int c = 0; c < 4; c++) {
        const int kc = c * KC;

        // ---- stage A chunk: 128 rows x 32 k, fp32 -> bf16 hi/lo, swizzled ----
        {
#pragma unroll
            for (int i = 0; i < 4; i++) {
                int idx = i * 256 + tid;
                int m = idx >> 3, q = idx & 7;
                int gm = mblk + m;
                float4 v = make_float4(0.f, 0.f, 0.f, 0.f);
                if (gm < N_NODES)
                    v = *reinterpret_cast<const float4*>(A + (size_t)gm * D + kc + q * 4);
                __nv_bfloat162 h01 = __float22bfloat162_rn(make_float2(v.x, v.y));
                __nv_bfloat162 h23 = __float22bfloat162_rn(make_float2(v.z, v.w));
                float2 lo01 = make_float2(v.x - __low2float(h01), v.y - __high2float(h01));
                float2 lo23 = make_float2(v.z - __low2float(h23), v.w - __high2float(h23));
                __nv_bfloat162 l01 = __float22bfloat162_rn(lo01);
                __nv_bfloat162 l23 = __float22bfloat162_rn(lo23);
                uint32_t sb = sw64((uint32_t)(m * 64 + q * 8));
                *reinterpret_cast<uint2*>(sAh + sb) =
                    make_uint2(*reinterpret_cast<uint32_t*>(&h01),
                               *reinterpret_cast<uint32_t*>(&h23));
                *reinterpret_cast<uint2*>(sAl + sb) =
                    make_uint2(*reinterpret_cast<uint32_t*>(&l01),
                               *reinterpret_cast<uint32_t*>(&l23));
            }
        }

        // ---- stage B chunk: copy bf16 W hi/lo [n][kofs+kc ..+32), swizzled ----
        {
#pragma unroll
            for (int i = 0; i < 2; i++) {
                int idx = i * 256 + tid;
                int n = idx >> 2, u = idx & 3;
                size_t srcoff = (size_t)n * KDIM + kofs + kc;   // bf16 elems
                uint32_t sb = sw64((uint32_t)(n * 64 + u * 16));
                *reinterpret_cast<uint4*>(sBh + sb) =
                    *reinterpret_cast<const uint4*>(
                        reinterpret_cast<const uint8_t*>(g_Wh) + srcoff * 2 + u * 16);
                *reinterpret_cast<uint4*>(sBl + sb) =
                    *reinterpret_cast<const uint4*>(
                        reinterpret_cast<const uint8_t*>(g_Wl) + srcoff * 2 + u * 16);
            }
        }
        __syncthreads();

        // ---- compute: 2 k-steps of 16 ----
#pragma unroll
        for (int ks = 0; ks < 2; ks++) {
            const int k0 = ks * 16;
            uint32_t Ah[2][4], Al[2][4];
#pragma unroll
            for (int f = 0; f < 2; f++) {
                int row = warp_m * 32 + f * 16 + (lsub & 1) * 8 + lr;
                int kb  = k0 + (lsub >> 1) * 8;
                uint32_t ofs = sw64((uint32_t)(row * 64 + kb * 2));
                ldsm_x4(Ah[f][0], Ah[f][1], Ah[f][2], Ah[f][3], bAh + ofs);
                ldsm_x4(Al[f][0], Al[f][1], Al[f][2], Al[f][3], bAl + ofs);
            }
#pragma unroll
            for (int np = 0; np < 4; np++) {
                int n  = warp_n * 64 + np * 16 + (lsub >> 1) * 8 + lr;
                int kb = k0 + (lsub & 1) * 8;
                uint32_t ofs = sw64((uint32_t)(n * 64 + kb * 2));
                uint32_t Bh[4], Bl[4];
                ldsm_x4(Bh[0], Bh[1], Bh[2], Bh[3], bBh + ofs);
                ldsm_x4(Bl[0], Bl[1], Bl[2], Bl[3], bBl + ofs);
#pragma unroll
                for (int f = 0; f < 2; f++) {
                    mma_bf16(acc[f][np * 2 + 0], Ah[f][0], Ah[f][1], Ah[f][2], Ah[f][3], Bh[0], Bh[1]);
                    mma_bf16(acc[f][np * 2 + 1], Ah[f][0], Ah[f][1], Ah[f][2], Ah[f][3], Bh[2], Bh[3]);
                    mma_bf16(acc[f][np * 2 + 0], Ah[f][0], Ah[f][1], Ah[f][2], Ah[f][3], Bl[0], Bl[1]);
                    mma_bf16(acc[f][np * 2 + 1], Ah[f][0], Ah[f][1], Ah[f][2], Ah[f][3], Bl[2], Bl[3]);
                    mma_bf16(acc[f][np * 2 + 0], Al[f][0], Al[f][1], Al[f][2], Al[f][3], Bh[0], Bh[1]);
                    mma_bf16(acc[f][np * 2 + 1], Al[f][0], Al[f][1], Al[f][2], Al[f][3], Bh[2], Bh[3]);
                }
            }
        }
        __syncthreads();
    }

    // ---- epilogue ----
    const int mbase = mblk + warp_m * 32 + (lane >> 2);
#pragma unroll
    for (int f = 0; f < 2; f++) {
        int row0 = mbase + f * 16;
        int row1 = row0 + 8;
#pragma unroll
        for (int t = 0; t < 8; t++) {
            int col = warp_n * 64 + t * 8 + (lane & 3) * 2;
            if (use_agg) {
                if (row0 < N_NODES) {
                    float2* p = reinterpret_cast<float2*>(out + (size_t)row0 * D + col);
                    float2 o = *p;
                    o.x += acc[f][t][0]; o.y += acc[f][t][1];
                    *p = o;
                }
                if (row1 < N_NODES) {
                    float2* p = reinterpret_cast<float2*>(out + (size_t)row1 * D + col);
                    float2 o = *p;
                    o.x += acc[f][t][2]; o.y += acc[f][t][3];
                    *p = o;
                }
            } else {
                float2 bv = *reinterpret_cast<const float2*>(bias + col);
                if (row0 < N_NODES) {
                    float2 o = make_float2(acc[f][t][0] + bv.x, acc[f][t][1] + bv.y);
                    *reinterpret_cast<float2*>(out + (size_t)row0 * D + col) = o;
                }
                if (row1 < N_NODES) {
                    float2 o = make_float2(acc[f][t][2] + bv.x, acc[f][t][3] + bv.y);
                    *reinterpret_cast<float2*>(out + (size_t)row1 * D + col) = o;
                }
            }
        }
    }
}

// ===========================================================================
// Launch: forked-stream graph
//   branch A (origin): zero -> hist -> scan -> fill -> aggregate
//   branch B (s2):     wsplit -> gemm part1 (out = H@W1 + b)
//   join -> gemm part2 (out += agg@W2)
// ===========================================================================
extern "C" void kernel_launch(void* const* d_in, const int* in_sizes, int n_in,
                              void* d_out, int out_size) {
    const float* H   = (const float*)d_in[0];
    const int*   src = (const int*)d_in[1];
    const int*   dst = (const int*)d_in[2];
    const float* W   = (const float*)d_in[3];
    const float* b   = (const float*)d_in[4];
    float*       out = (float*)d_out;

    // lazily-created host-side resources (no device memory involved)
    static cudaStream_t s2 = nullptr;
    static cudaEvent_t evFork = nullptr, evJoin = nullptr;
    if (!s2) {
        cudaStreamCreateWithFlags(&s2, cudaStreamNonBlocking);
        cudaEventCreateWithFlags(&evFork, cudaEventDisableTiming);
        cudaEventCreateWithFlags(&evJoin, cudaEventDisableTiming);
    }

    const int nb_nodes = (N_NODES + 255) / 256;
    const int nb_edges = (N_EDGES + 255) / 256;
    const int nb_scan  = (N_NODES + 1023) / 1024;   // 98
    const int nb_gemm  = (N_NODES + 127) / 128;     // 782

    // fork
    cudaEventRecord(evFork, 0);
    cudaStreamWaitEvent(s2, evFork, 0);

    // branch B: W split + GEMM part 1 (independent of aggregation)
    wsplit_kernel<<<(128 * KDIM + 255) / 256, 256, 0, s2>>>(W);
    gemm_half_kernel<<<nb_gemm, 256, 0, s2>>>(H, b, out, 0);
    cudaEventRecord(evJoin, s2);

    // branch A: CSR build + aggregate
    zero_deg_kernel<<<nb_nodes, 256>>>();
    hist_kernel<<<nb_edges, 256>>>(src);
    scan_partial_kernel<<<nb_scan, 1024>>>();
    scan_bsums_kernel<<<1, 128>>>(nb_scan);
    scan_add_kernel<<<nb_nodes, 256>>>();
    fill_adj_kernel<<<nb_edges, 256>>>(src, dst);
    aggregate_kernel<<<(N_NODES * 32 + 255) / 256, 256>>>(H);

    // join, then GEMM part 2
    cudaStreamWaitEvent(0, evJoin, 0);
    gemm_half_kernel<<<nb_gemm, 256>>>(H, b, out, 1);
}

// round 6
// speedup vs baseline: 1.3062x; 1.3062x over previous
#include <cuda_runtime.h>
#include <cuda_bf16.h>
#include <float.h>
#include <stdint.h>

#define N_NODES 100000
#define N_EDGES 1600000
#define D 128
#define KDIM 256

// ---------------------------------------------------------------------------
// Device scratch (static per harness rules)
// ---------------------------------------------------------------------------
__device__ int   g_deg[N_NODES];
__device__ int   g_off[N_NODES];      // partial (pre-bsum) exclusive offsets
__device__ int   g_rank[N_EDGES];
__device__ int   g_adj[N_EDGES];
__device__ int   g_bsum[128];
__device__ int   g_bsumoff[128];
__device__ __align__(16) __nv_bfloat16 g_Wh[128 * KDIM];  // W split hi
__device__ __align__(16) __nv_bfloat16 g_Wl[128 * KDIM];  // W split lo

// ===========================================================================
// CSR build
// ===========================================================================
__global__ void __launch_bounds__(256) zero_deg_kernel() {
    int i = blockIdx.x * blockDim.x + threadIdx.x;
    if (i < N_NODES) g_deg[i] = 0;
}

// histogram + per-edge rank; 4 edges/thread for MLP
__global__ void __launch_bounds__(256) hist_kernel(const int* __restrict__ src) {
    int i = blockIdx.x * blockDim.x + threadIdx.x;   // over E/4
    if (i < N_EDGES / 4) {
        int4 s = reinterpret_cast<const int4*>(src)[i];
        int4 r;
        r.x = atomicAdd(&g_deg[s.x], 1);
        r.y = atomicAdd(&g_deg[s.y], 1);
        r.z = atomicAdd(&g_deg[s.z], 1);
        r.w = atomicAdd(&g_deg[s.w], 1);
        reinterpret_cast<int4*>(g_rank)[i] = r;
    }
}

__global__ void __launch_bounds__(1024) scan_partial_kernel() {
    __shared__ int s[1024];
    int i = blockIdx.x * 1024 + threadIdx.x;
    int v = (i < N_NODES) ? g_deg[i] : 0;
    s[threadIdx.x] = v;
    __syncthreads();
#pragma unroll
    for (int ofs = 1; ofs < 1024; ofs <<= 1) {
        int t = (threadIdx.x >= ofs) ? s[threadIdx.x - ofs] : 0;
        __syncthreads();
        s[threadIdx.x] += t;
        __syncthreads();
    }
    if (i < N_NODES) g_off[i] = s[threadIdx.x] - v;
    if (threadIdx.x == 1023) g_bsum[blockIdx.x] = s[1023];
}

__global__ void __launch_bounds__(128) scan_bsums_kernel(int nblocks) {
    __shared__ int s[128];
    int v = (threadIdx.x < nblocks) ? g_bsum[threadIdx.x] : 0;
    s[threadIdx.x] = v;
    __syncthreads();
#pragma unroll
    for (int ofs = 1; ofs < 128; ofs <<= 1) {
        int t = (threadIdx.x >= ofs) ? s[threadIdx.x - ofs] : 0;
        __syncthreads();
        s[threadIdx.x] += t;
        __syncthreads();
    }
    g_bsumoff[threadIdx.x] = s[threadIdx.x] - v;
}

// atomic-free scatter (rank precomputed); offsets patched with bsumoff here
__global__ void __launch_bounds__(256) fill_adj_kernel(const int* __restrict__ src,
                                                       const int* __restrict__ dst) {
    int i = blockIdx.x * blockDim.x + threadIdx.x;   // over E/4
    if (i < N_EDGES / 4) {
        int4 s = reinterpret_cast<const int4*>(src)[i];
        int4 d = reinterpret_cast<const int4*>(dst)[i];
        int4 r = reinterpret_cast<const int4*>(g_rank)[i];
        g_adj[g_off[s.x] + g_bsumoff[s.x >> 10] + r.x] = d.x;
        g_adj[g_off[s.y] + g_bsumoff[s.y >> 10] + r.y] = d.y;
        g_adj[g_off[s.z] + g_bsumoff[s.z >> 10] + r.z] = d.z;
        g_adj[g_off[s.w] + g_bsumoff[s.w >> 10] + r.w] = d.w;
    }
}

// ===========================================================================
// W hi/lo bf16 split
// ===========================================================================
__global__ void __launch_bounds__(256) wsplit_kernel(const float* __restrict__ W) {
    int i = blockIdx.x * blockDim.x + threadIdx.x;
    if (i < 128 * KDIM) {
        float v = W[i];
        __nv_bfloat16 h = __float2bfloat16_rn(v);
        g_Wh[i] = h;
        g_Wl[i] = __float2bfloat16_rn(v - __bfloat162float(h));
    }
}

// ===========================================================================
// Fused aggregate + GEMM
//   Phase 1: CTA computes agg (segment-max) for its 128 rows, storing bf16
//            hi/lo DIRECTLY in swizzled ldmatrix layout in smem (4 k-chunks).
//   Phase 2: out[m][n] = sum_k [H|agg][m][k] * W[n][k] + b[n]
//            8 k-chunks of 32; chunks 0-3 stage from H, 4-7 use phase-1 smem.
//   3-pass bf16 hi/lo split HMMA, fp32 accumulate.
// ===========================================================================
__device__ __forceinline__ uint32_t smem_u32(const void* p) {
    uint32_t a;
    asm("{ .reg .u64 t; cvta.to.shared.u64 t, %1; cvt.u32.u64 %0, t; }"
        : "=r"(a) : "l"(p));
    return a;
}

__device__ __forceinline__ uint32_t sw64(uint32_t b) { return b ^ ((b >> 3) & 0x30); }

__device__ __forceinline__ void ldsm_x4(uint32_t& r0, uint32_t& r1, uint32_t& r2,
                                        uint32_t& r3, uint32_t addr) {
    asm volatile("ldmatrix.sync.aligned.m8n8.x4.shared.b16 {%0,%1,%2,%3}, [%4];"
                 : "=r"(r0), "=r"(r1), "=r"(r2), "=r"(r3) : "r"(addr));
}

__device__ __forceinline__ void mma_bf16(float* c, uint32_t a0, uint32_t a1,
                                         uint32_t a2, uint32_t a3,
                                         uint32_t b0, uint32_t b1) {
    asm volatile(
        "mma.sync.aligned.m16n8k16.row.col.f32.bf16.bf16.f32 "
        "{%0,%1,%2,%3},{%4,%5,%6,%7},{%8,%9},{%0,%1,%2,%3};"
        : "+f"(c[0]), "+f"(c[1]), "+f"(c[2]), "+f"(c[3])
        : "r"(a0), "r"(a1), "r"(a2), "r"(a3), "r"(b0), "r"(b1));
}

__device__ __forceinline__ float4 max4(float4 a, float4 b) {
    return make_float4(fmaxf(a.x, b.x), fmaxf(a.y, b.y),
                       fmaxf(a.z, b.z), fmaxf(a.w, b.w));
}

__device__ __forceinline__ void split_pair(float2 v, uint32_t& hi, uint32_t& lo) {
    __nv_bfloat162 h = __float22bfloat162_rn(v);
    float2 r = make_float2(v.x - __low2float(h), v.y - __high2float(h));
    __nv_bfloat162 l = __float22bfloat162_rn(r);
    hi = *reinterpret_cast<uint32_t*>(&h);
    lo = *reinterpret_cast<uint32_t*>(&l);
}

// dynamic smem layout (96 KB total):
//   [0,      65536): aggC[4 chunks][hi 8KB | lo 8KB]
//   [65536,  73728): sAh   (H-chunk staging)
//   [73728,  81920): sAl
//   [81920,  90112): sBh
//   [90112,  98304): sBl
#define SM_AGG   0
#define SM_AH    65536
#define SM_AL    73728
#define SM_BH    81920
#define SM_BL    90112
#define SM_TOTAL 98304

__global__ void __launch_bounds__(256, 2) fused_kernel(
    const float* __restrict__ H,
    const float* __restrict__ bias,
    float* __restrict__ out)
{
    extern __shared__ __align__(16) uint8_t smem[];

    const int tid    = threadIdx.x;
    const int wid    = tid >> 5;
    const int lane   = tid & 31;
    const int warp_m = wid >> 1;
    const int warp_n = wid & 1;
    const int mblk   = blockIdx.x * 128;

    // ------------------- Phase 1: aggregate into swizzled smem -------------
    {
        const int q  = lane & 7;            // quad within chunk
        const int ch = lane >> 3;           // k-chunk (0..3) this lane feeds
        uint8_t* aggHi = smem + SM_AGG + ch * 16384;
        uint8_t* aggLo = aggHi + 8192;

        for (int i = 0; i < 16; i++) {
            int mloc  = wid * 16 + i;
            int gnode = mblk + mloc;
            float4 m = make_float4(-FLT_MAX, -FLT_MAX, -FLT_MAX, -FLT_MAX);
            int deg = 0;
            if (gnode < N_NODES) {
                int off = g_off[gnode] + g_bsumoff[gnode >> 10];
                deg = g_deg[gnode];
                int j = 0;
                for (; j + 4 <= deg; j += 4) {
                    int n0 = g_adj[off + j + 0];
                    int n1 = g_adj[off + j + 1];
                    int n2 = g_adj[off + j + 2];
                    int n3 = g_adj[off + j + 3];
                    float4 v0 = *reinterpret_cast<const float4*>(H + (size_t)n0 * D + lane * 4);
                    float4 v1 = *reinterpret_cast<const float4*>(H + (size_t)n1 * D + lane * 4);
                    float4 v2 = *reinterpret_cast<const float4*>(H + (size_t)n2 * D + lane * 4);
                    float4 v3 = *reinterpret_cast<const float4*>(H + (size_t)n3 * D + lane * 4);
                    m = max4(m, max4(max4(v0, v1), max4(v2, v3)));
                }
                for (; j < deg; j++) {
                    int n0 = g_adj[off + j];
                    m = max4(m, *reinterpret_cast<const float4*>(H + (size_t)n0 * D + lane * 4));
                }
            }
            if (deg == 0) m = make_float4(0.f, 0.f, 0.f, 0.f);

            uint32_t h01, l01, h23, l23;
            split_pair(make_float2(m.x, m.y), h01, l01);
            split_pair(make_float2(m.z, m.w), h23, l23);
            uint32_t sb = sw64((uint32_t)(mloc * 64 + q * 8));
            *reinterpret_cast<uint2*>(aggHi + sb) = make_uint2(h01, h23);
            *reinterpret_cast<uint2*>(aggLo + sb) = make_uint2(l01, l23);
        }
    }
    __syncthreads();

    // ------------------- Phase 2: GEMM over 8 k-chunks ---------------------
    const uint32_t bAh0 = smem_u32(smem + SM_AH);
    const uint32_t bAl0 = smem_u32(smem + SM_AL);
    const uint32_t bBh  = smem_u32(smem + SM_BH);
    const uint32_t bBl  = smem_u32(smem + SM_BL);
    const uint32_t bAgg = smem_u32(smem + SM_AGG);

    const int lsub = lane >> 3;
    const int lr   = lane & 7;

    float acc[2][8][4];
#pragma unroll
    for (int f = 0; f < 2; f++)
#pragma unroll
        for (int t = 0; t < 8; t++)
#pragma unroll
            for (int i = 0; i < 4; i++) acc[f][t][i] = 0.f;

    for (int c = 0; c < 8; c++) {
        const int kc = c * 32;            // global W column base

        // ---- stage A (H chunks only) ----
        if (c < 4) {
#pragma unroll
            for (int i = 0; i < 4; i++) {
                int idx = i * 256 + tid;
                int m = idx >> 3, q = idx & 7;
                int gm = mblk + m;
                float4 v = make_float4(0.f, 0.f, 0.f, 0.f);
                if (gm < N_NODES)
                    v = *reinterpret_cast<const float4*>(H + (size_t)gm * D + kc + q * 4);
                uint32_t h01, l01, h23, l23;
                split_pair(make_float2(v.x, v.y), h01, l01);
                split_pair(make_float2(v.z, v.w), h23, l23);
                uint32_t sb = sw64((uint32_t)(m * 64 + q * 8));
                *reinterpret_cast<uint2*>(smem + SM_AH + sb) = make_uint2(h01, h23);
                *reinterpret_cast<uint2*>(smem + SM_AL + sb) = make_uint2(l01, l23);
            }
        }

        // ---- stage B chunk ----
        {
#pragma unroll
            for (int i = 0; i < 2; i++) {
                int idx = i * 256 + tid;
                int n = idx >> 2, u = idx & 3;
                size_t srcoff = (size_t)n * KDIM + kc;   // bf16 elems
                uint32_t sb = sw64((uint32_t)(n * 64 + u * 16));
                *reinterpret_cast<uint4*>(smem + SM_BH + sb) =
                    *reinterpret_cast<const uint4*>(
                        reinterpret_cast<const uint8_t*>(g_Wh) + srcoff * 2 + u * 16);
                *reinterpret_cast<uint4*>(smem + SM_BL + sb) =
                    *reinterpret_cast<const uint4*>(
                        reinterpret_cast<const uint8_t*>(g_Wl) + srcoff * 2 + u * 16);
            }
        }
        __syncthreads();

        const uint32_t aH = (c < 4) ? bAh0 : (bAgg + (uint32_t)(c - 4) * 16384u);
        const uint32_t aL = (c < 4) ? bAl0 : (aH + 8192u);

        // ---- compute: 2 k-steps of 16 ----
#pragma unroll
        for (int ks = 0; ks < 2; ks++) {
            const int k0 = ks * 16;
            uint32_t Ah[2][4], Al[2][4];
#pragma unroll
            for (int f = 0; f < 2; f++) {
                int row = warp_m * 32 + f * 16 + (lsub & 1) * 8 + lr;
                int kb  = k0 + (lsub >> 1) * 8;
                uint32_t ofs = sw64((uint32_t)(row * 64 + kb * 2));
                ldsm_x4(Ah[f][0], Ah[f][1], Ah[f][2], Ah[f][3], aH + ofs);
                ldsm_x4(Al[f][0], Al[f][1], Al[f][2], Al[f][3], aL + ofs);
            }
#pragma unroll
            for (int np = 0; np < 4; np++) {
                int n  = warp_n * 64 + np * 16 + (lsub >> 1) * 8 + lr;
                int kb = k0 + (lsub & 1) * 8;
                uint32_t ofs = sw64((uint32_t)(n * 64 + kb * 2));
                uint32_t Bh[4], Bl[4];
                ldsm_x4(Bh[0], Bh[1], Bh[2], Bh[3], bBh + ofs);
                ldsm_x4(Bl[0], Bl[1], Bl[2], Bl[3], bBl + ofs);
#pragma unroll
                for (int f = 0; f < 2; f++) {
                    mma_bf16(acc[f][np * 2 + 0], Ah[f][0], Ah[f][1], Ah[f][2], Ah[f][3], Bh[0], Bh[1]);
                    mma_bf16(acc[f][np * 2 + 1], Ah[f][0], Ah[f][1], Ah[f][2], Ah[f][3], Bh[2], Bh[3]);
                    mma_bf16(acc[f][np * 2 + 0], Ah[f][0], Ah[f][1], Ah[f][2], Ah[f][3], Bl[0], Bl[1]);
                    mma_bf16(acc[f][np * 2 + 1], Ah[f][0], Ah[f][1], Ah[f][2], Ah[f][3], Bl[2], Bl[3]);
                    mma_bf16(acc[f][np * 2 + 0], Al[f][0], Al[f][1], Al[f][2], Al[f][3], Bh[0], Bh[1]);
                    mma_bf16(acc[f][np * 2 + 1], Al[f][0], Al[f][1], Al[f][2], Al[f][3], Bh[2], Bh[3]);
                }
            }
        }
        __syncthreads();
    }

    // ---- epilogue: add bias, store ----
    const int mbase = mblk + warp_m * 32 + (lane >> 2);
#pragma unroll
    for (int f = 0; f < 2; f++) {
        int row0 = mbase + f * 16;
        int row1 = row0 + 8;
#pragma unroll
        for (int t = 0; t < 8; t++) {
            int col = warp_n * 64 + t * 8 + (lane & 3) * 2;
            float2 bv = *reinterpret_cast<const float2*>(bias + col);
            if (row0 < N_NODES) {
                float2 o = make_float2(acc[f][t][0] + bv.x, acc[f][t][1] + bv.y);
                *reinterpret_cast<float2*>(out + (size_t)row0 * D + col) = o;
            }
            if (row1 < N_NODES) {
                float2 o = make_float2(acc[f][t][2] + bv.x, acc[f][t][3] + bv.y);
                *reinterpret_cast<float2*>(out + (size_t)row1 * D + col) = o;
            }
        }
    }
}

// ===========================================================================
// Launch (single stream; R5 showed stream forking loses to contention)
// ===========================================================================
extern "C" void kernel_launch(void* const* d_in, const int* in_sizes, int n_in,
                              void* d_out, int out_size) {
    const float* H   = (const float*)d_in[0];
    const int*   src = (const int*)d_in[1];
    const int*   dst = (const int*)d_in[2];
    const float* W   = (const float*)d_in[3];
    const float* b   = (const float*)d_in[4];
    float*       out = (float*)d_out;

    cudaFuncSetAttribute(fused_kernel,
                         cudaFuncAttributeMaxDynamicSharedMemorySize, SM_TOTAL);

    const int nb_nodes = (N_NODES + 255) / 256;
    const int nb_e4    = (N_EDGES / 4 + 255) / 256;
    const int nb_scan  = (N_NODES + 1023) / 1024;   // 98
    const int nb_gemm  = (N_NODES + 127) / 128;     // 782

    wsplit_kernel<<<(128 * KDIM + 255) / 256, 256>>>(W);
    zero_deg_kernel<<<nb_nodes, 256>>>();
    hist_kernel<<<nb_e4, 256>>>(src);
    scan_partial_kernel<<<nb_scan, 1024>>>();
    scan_bsums_kernel<<<1, 128>>>(nb_scan);
    fill_adj_kernel<<<nb_e4, 256>>>(src, dst);

    fused_kernel<<<nb_gemm, 256, SM_TOTAL>>>(H, b, out);
}